// round 15
// baseline (speedup 1.0000x reference)
#include <cuda_runtime.h>
#include <cuda_bf16.h>
#include <math.h>

namespace {

constexpr int C = 256, H = 4, HD = 64, L = 6, FC = 1024, OUT = 192;
constexpr int B = 8, T = 1024, BT = B * T, NREL = 9;

typedef __nv_bfloat16 bf16;

// ---------------- weight pair storage (QKV concatenated per layer) ----------------
constexpr size_t OFF_QKV = 0;
constexpr size_t OFF_WO  = (size_t)L * 3 * C * C;
constexpr size_t OFF_F1  = OFF_WO + (size_t)L * C * C;
constexpr size_t OFF_F2  = OFF_F1 + (size_t)L * C * FC;
constexpr size_t OFF_PJ  = OFF_F2 + (size_t)L * FC * C;
constexpr size_t WTOT    = OFF_PJ + (size_t)2 * OUT * C;

__device__ bf16 g_wb[WTOT];
__device__ bf16 g_ws[WTOT];

// ---------------- activation scratch ----------------
__device__ float g_x[BT * C];
__device__ bf16 g_xb[BT * C], g_xs[BT * C];
__device__ bf16 g_qb[BT * C], g_qs[BT * C];
__device__ bf16 g_kb[BT * C], g_ks[BT * C];
__device__ bf16 g_vb[BT * C], g_vs[BT * C];
__device__ bf16 g_ab[BT * C], g_as[BT * C];
__device__ bf16 g_fb[BT * FC], g_fs[BT * FC];

// ---------------- helpers ----------------
__device__ __forceinline__ void cvt2(float a, float b, unsigned& ub, unsigned& us) {
    __nv_bfloat162 hb, hs;
    hb.x = __float2bfloat16_rn(a);
    hb.y = __float2bfloat16_rn(b);
    float ra = a - __bfloat162float(hb.x);
    float rb = b - __bfloat162float(hb.y);
    hs.x = __float2bfloat16_rn(ra);
    hs.y = __float2bfloat16_rn(rb);
    ub = *reinterpret_cast<unsigned*>(&hb);
    us = *reinterpret_cast<unsigned*>(&hs);
}

__device__ __forceinline__ void mma16816(float c[4], const unsigned a[4], const unsigned b2[2]) {
    asm volatile(
        "mma.sync.aligned.m16n8k16.row.col.f32.bf16.bf16.f32 "
        "{%0,%1,%2,%3}, {%4,%5,%6,%7}, {%8,%9}, {%0,%1,%2,%3};\n"
        : "+f"(c[0]), "+f"(c[1]), "+f"(c[2]), "+f"(c[3])
        : "r"(a[0]), "r"(a[1]), "r"(a[2]), "r"(a[3]), "r"(b2[0]), "r"(b2[1]));
}

__device__ __forceinline__ void ldsm_x4(unsigned& r0, unsigned& r1, unsigned& r2, unsigned& r3,
                                        const void* p) {
    unsigned addr = (unsigned)__cvta_generic_to_shared(p);
    asm volatile("ldmatrix.sync.aligned.m8n8.x4.shared.b16 {%0,%1,%2,%3}, [%4];"
                 : "=r"(r0), "=r"(r1), "=r"(r2), "=r"(r3)
                 : "r"(addr));
}
__device__ __forceinline__ void ldsm_x2(unsigned& r0, unsigned& r1, const void* p) {
    unsigned addr = (unsigned)__cvta_generic_to_shared(p);
    asm volatile("ldmatrix.sync.aligned.m8n8.x2.shared.b16 {%0,%1}, [%2];"
                 : "=r"(r0), "=r"(r1)
                 : "r"(addr));
}
__device__ __forceinline__ void ldsm_x4_t(unsigned& r0, unsigned& r1, unsigned& r2, unsigned& r3,
                                          const void* p) {
    unsigned addr = (unsigned)__cvta_generic_to_shared(p);
    asm volatile("ldmatrix.sync.aligned.m8n8.x4.trans.shared.b16 {%0,%1,%2,%3}, [%4];"
                 : "=r"(r0), "=r"(r1), "=r"(r2), "=r"(r3)
                 : "r"(addr));
}
__device__ __forceinline__ void cp16(void* s, const void* g) {
    unsigned a = (unsigned)__cvta_generic_to_shared(s);
    asm volatile("cp.async.cg.shared.global [%0], [%1], 16;" :: "r"(a), "l"(g));
}
#define CP_COMMIT() asm volatile("cp.async.commit_group;")

// =====================================================================
//  prep kernel (unchanged from R10)
// =====================================================================
__device__ void wconv_blk(const float* __restrict__ w, bf16* __restrict__ ob,
                          bf16* __restrict__ os, int K, int N, size_t lstride, int bx) {
    __shared__ float tile[32][33];
    int nx = N / 32, ny = K / 32;
    int l = bx / (nx * ny);
    int rem = bx % (nx * ny);
    int y = rem / nx, x = rem % nx;
    const float* src = w + (size_t)l * K * N;
    int k0 = y * 32, n0 = x * 32;
    int tx = threadIdx.x & 31, ty = threadIdx.x >> 5;
#pragma unroll
    for (int i = 0; i < 32; i += 8)
        tile[ty + i][tx] = src[(size_t)(k0 + ty + i) * N + n0 + tx];
    __syncthreads();
#pragma unroll
    for (int i = 0; i < 32; i += 8) {
        float v = tile[tx][ty + i];
        size_t o = (size_t)l * lstride + (size_t)(n0 + ty + i) * K + k0 + tx;
        bf16 hb = __float2bfloat16_rn(v);
        ob[o] = hb;
        os[o] = __float2bfloat16_rn(v - __bfloat162float(hb));
    }
}

__global__ void prep_kernel(const float* __restrict__ Wq, const float* __restrict__ Wk,
                            const float* __restrict__ Wv, const float* __restrict__ Wo,
                            const float* __restrict__ fw1, const float* __restrict__ fw2,
                            const float* __restrict__ pw, const float* __restrict__ emb,
                            const int* __restrict__ toks) {
    int bx = blockIdx.x;
    if (bx < 384) { wconv_blk(Wq, g_wb + OFF_QKV, g_ws + OFF_QKV, C, C, (size_t)3 * C * C, bx); return; }
    bx -= 384;
    if (bx < 384) { wconv_blk(Wk, g_wb + OFF_QKV + C * C, g_ws + OFF_QKV + C * C, C, C, (size_t)3 * C * C, bx); return; }
    bx -= 384;
    if (bx < 384) { wconv_blk(Wv, g_wb + OFF_QKV + 2 * C * C, g_ws + OFF_QKV + 2 * C * C, C, C, (size_t)3 * C * C, bx); return; }
    bx -= 384;
    if (bx < 384) { wconv_blk(Wo, g_wb + OFF_WO, g_ws + OFF_WO, C, C, (size_t)C * C, bx); return; }
    bx -= 384;
    if (bx < 1536) { wconv_blk(fw1, g_wb + OFF_F1, g_ws + OFF_F1, C, FC, (size_t)C * FC, bx); return; }
    bx -= 1536;
    if (bx < 1536) { wconv_blk(fw2, g_wb + OFF_F2, g_ws + OFF_F2, FC, C, (size_t)FC * C, bx); return; }
    bx -= 1536;
    if (bx < 384) {
        int i = bx * 256 + threadIdx.x;
        if (i < 2 * OUT * C) {
            float v = pw[i];
            bf16 hb = __float2bfloat16_rn(v);
            g_wb[OFF_PJ + i] = hb;
            g_ws[OFF_PJ + i] = __float2bfloat16_rn(v - __bfloat162float(hb));
        }
        return;
    }
    bx -= 384;
#pragma unroll
    for (int j = 0; j < 8; j++) {
        int idx = bx * 2048 + j * 256 + threadIdx.x;
        int bt = idx >> 8, c = idx & 255;
        float v = emb[(size_t)toks[bt] * C + c] * 16.0f;
        g_x[idx] = v;
        bf16 hb = __float2bfloat16_rn(v);
        g_xb[idx] = hb;
        g_xs[idx] = __float2bfloat16_rn(v - __bfloat162float(hb));
    }
}

// =====================================================================
//  Pair-input bf16x3 GEMM: 128x128 tile (QKV / FFN1 / stats)
// =====================================================================
constexpr int APITCH = 40;
constexpr int TSZ = 128 * APITCH;
constexpr int SMEM_BYTES = 8 * TSZ * (int)sizeof(bf16);  // 81920

template <int MODE>
__global__ __launch_bounds__(256, 2) void mma_gemm_p(
    const bf16* __restrict__ Ab, const bf16* __restrict__ As2,
    const bf16* __restrict__ Bb, const bf16* __restrict__ Bs2,
    const float* __restrict__ bias, const float* __restrict__ bias2,
    const float* __restrict__ bias3, float* __restrict__ outf,
    bf16* __restrict__ outb, bf16* __restrict__ outs, float* __restrict__ out2,
    int M, int N, int K, float alpha, int relu, const int* __restrict__ lens) {
    extern __shared__ bf16 dsm[];
    bf16* As_b = dsm;
    bf16* As_s = dsm + 2 * TSZ;
    bf16* Bs_b = dsm + 4 * TSZ;
    bf16* Bs_s = dsm + 6 * TSZ;

    const int tid = threadIdx.x;
    const int lane = tid & 31, wid = tid >> 5;
    const int wm = wid >> 1, wn = wid & 1;
    const int g = lane >> 2, tig = lane & 3;
    const int m0 = blockIdx.y * 128, n0 = blockIdx.x * 128;

    const int ar = tid >> 1, akh = (tid & 1) * 16;

    const int lane7 = lane & 7;
    const int arow = wm * 32 + lane7 + ((lane & 8) ? 8 : 0);
    const int acolsel = (lane & 16) ? 8 : 0;
    const int brow = lane7 + ((lane & 16) ? 8 : 0);
    const int bcolsel = (lane & 8) ? 8 : 0;

    float acc[2][8][4] = {};

    auto load_st = [&](int k0, int st) {
        size_t ai = (size_t)(m0 + ar) * K + k0 + akh;
        size_t bi = (size_t)(n0 + ar) * K + k0 + akh;
        int so = st * TSZ + ar * APITCH + akh;
        cp16(As_b + so, Ab + ai);
        cp16(As_b + so + 8, Ab + ai + 8);
        cp16(As_s + so, As2 + ai);
        cp16(As_s + so + 8, As2 + ai + 8);
        cp16(Bs_b + so, Bb + bi);
        cp16(Bs_b + so + 8, Bb + bi + 8);
        cp16(Bs_s + so, Bs2 + bi);
        cp16(Bs_s + so + 8, Bs2 + bi + 8);
    };

    const int KT = K >> 5;
    load_st(0, 0);
    CP_COMMIT();

    for (int kt = 0; kt < KT; kt++) {
        if (kt + 1 < KT) {
            load_st((kt + 1) * 32, (kt + 1) & 1);
            CP_COMMIT();
            asm volatile("cp.async.wait_group 1;");
        } else {
            CP_COMMIT();
            asm volatile("cp.async.wait_group 0;");
        }
        __syncthreads();
        const int buf = kt & 1;
        const bf16* ab_base = As_b + buf * TSZ;
        const bf16* as_base = As_s + buf * TSZ;
        const bf16* bb_base = Bs_b + buf * TSZ;
        const bf16* bs_base = Bs_s + buf * TSZ;
#pragma unroll
        for (int kk = 0; kk < 32; kk += 16) {
            unsigned ab[2][4], as_[2][4], bb[8][2], bs_[8][2];
#pragma unroll
            for (int am = 0; am < 2; am++) {
                ldsm_x4(ab[am][0], ab[am][1], ab[am][2], ab[am][3],
                        ab_base + (arow + am * 16) * APITCH + kk + acolsel);
                ldsm_x4(as_[am][0], as_[am][1], as_[am][2], as_[am][3],
                        as_base + (arow + am * 16) * APITCH + kk + acolsel);
            }
#pragma unroll
            for (int p = 0; p < 4; p++) {
                ldsm_x4(bb[2 * p][0], bb[2 * p][1], bb[2 * p + 1][0], bb[2 * p + 1][1],
                        bb_base + (wn * 64 + p * 16 + brow) * APITCH + kk + bcolsel);
                ldsm_x4(bs_[2 * p][0], bs_[2 * p][1], bs_[2 * p + 1][0], bs_[2 * p + 1][1],
                        bs_base + (wn * 64 + p * 16 + brow) * APITCH + kk + bcolsel);
            }
#pragma unroll
            for (int am = 0; am < 2; am++)
#pragma unroll
                for (int an = 0; an < 8; an++) {
                    mma16816(acc[am][an], ab[am], bb[an]);
                    mma16816(acc[am][an], ab[am], bs_[an]);
                    mma16816(acc[am][an], as_[am], bb[an]);
                }
        }
        __syncthreads();
    }

    // ---------------- epilogue ----------------
    int tgt = 0;
    const float* biasp = bias;
    bf16* tob = outb;
    bf16* tos = outs;
    float al = alpha;
    if constexpr (MODE == 1) {
        tgt = n0 >> 8;
        biasp = (tgt == 0) ? bias : (tgt == 1 ? bias2 : bias3);
        tob = (tgt == 0) ? g_qb : (tgt == 1 ? g_kb : g_vb);
        tos = (tgt == 0) ? g_qs : (tgt == 1 ? g_ks : g_vs);
        al = (tgt == 0) ? 0.125f : 1.0f;
    }

#pragma unroll
    for (int am = 0; am < 2; am++) {
#pragma unroll
        for (int rr = 0; rr < 2; rr++) {
            int row = m0 + wm * 32 + am * 16 + g + rr * 8;
#pragma unroll
            for (int an = 0; an < 8; an++) {
                int col0 = n0 + wn * 64 + an * 8 + 2 * tig;
                if constexpr (MODE == 0) {
                    float v0 = (acc[am][an][rr * 2 + 0] + bias[col0]) * alpha;
                    float v1 = (acc[am][an][rr * 2 + 1] + bias[col0 + 1]) * alpha;
                    if (relu) { v0 = fmaxf(v0, 0.f); v1 = fmaxf(v1, 0.f); }
                    if (outf) {
                        outf[(size_t)row * N + col0] = v0;
                        outf[(size_t)row * N + col0 + 1] = v1;
                    }
                    if (outb) {
                        unsigned ub, us;
                        cvt2(v0, v1, ub, us);
                        *reinterpret_cast<unsigned*>(&outb[(size_t)row * N + col0]) = ub;
                        *reinterpret_cast<unsigned*>(&outs[(size_t)row * N + col0]) = us;
                    }
                } else if constexpr (MODE == 1) {
                    int lc = col0 - tgt * 256;
                    float v0 = (acc[am][an][rr * 2 + 0] + biasp[lc]) * al;
                    float v1 = (acc[am][an][rr * 2 + 1] + biasp[lc + 1]) * al;
                    unsigned ub, us;
                    cvt2(v0, v1, ub, us);
                    *reinterpret_cast<unsigned*>(&tob[(size_t)row * C + lc]) = ub;
                    *reinterpret_cast<unsigned*>(&tos[(size_t)row * C + lc]) = us;
                } else {  // MODE 3
                    int bb2 = row >> 10, tt = row & (T - 1);
                    float mk = (tt < lens[bb2]) ? 1.0f : 0.0f;
#pragma unroll
                    for (int cc = 0; cc < 2; cc++) {
                        int col = col0 + cc;
                        float vv = (acc[am][an][rr * 2 + cc] + bias[col]) * mk;
                        if (col < OUT)
                            outf[((size_t)bb2 * OUT + col) * T + tt] = vv;
                        else
                            out2[((size_t)bb2 * OUT + (col - OUT)) * T + tt] = vv;
                    }
                }
            }
        }
    }
}

// =====================================================================
//  LN-fused GEMM: 32M x 256N tile, BK=32, 256 thr, 2-stage cp.async.
//  out = LN(residual + A@B^T + bias) * gamma + beta  [* mask]
//  Writes fp32 x + bf16 pair. grid = BT/32 = 256 blocks, occ 2.
// =====================================================================
constexpr int LG_ATS = 32 * APITCH;    // 1280
constexpr int LG_BTS = 256 * APITCH;   // 10240
constexpr int LG_SMEM = (4 * LG_ATS + 4 * LG_BTS) * (int)sizeof(bf16);  // 92160

__global__ __launch_bounds__(256, 2) void ln_gemm(
    const bf16* __restrict__ Ab, const bf16* __restrict__ As2,
    const bf16* __restrict__ Bb, const bf16* __restrict__ Bs2,
    const float* __restrict__ bias, const float* __restrict__ gamma,
    const float* __restrict__ beta, float* __restrict__ xres,
    bf16* __restrict__ outb, bf16* __restrict__ outs,
    int K, int apply_mask, const int* __restrict__ lens) {
    extern __shared__ bf16 dsm[];
    bf16* As_b = dsm;                                // [2][32][40]
    bf16* As_s = dsm + 2 * LG_ATS;
    bf16* Bs_b = dsm + 4 * LG_ATS;                   // [2][256][40]
    bf16* Bs_s = dsm + 4 * LG_ATS + 2 * LG_BTS;
    __shared__ float red_s[4][32], red_q[4][32];

    const int tid = threadIdx.x;
    const int lane = tid & 31, wid = tid >> 5;
    const int wm = wid >> 2, wn = wid & 3;          // 2 x 4 warps
    const int g = lane >> 2, tig = lane & 3;
    const unsigned qm = 0xFu << (lane & 28);
    const int m0 = blockIdx.x * 32;

    const int lane7 = lane & 7;
    const int arow = wm * 16 + lane7 + ((lane & 8) ? 8 : 0);
    const int acolsel = (lane & 16) ? 8 : 0;
    const int brow = lane7 + ((lane & 16) ? 8 : 0);
    const int bcolsel = (lane & 8) ? 8 : 0;

    float acc[8][4] = {};

    // A: 32x32 per tensor = 128 cp16; threads 0-127 -> big, 128-255 -> small
    const int at = tid & 127;
    const int ar = at >> 2, ak = (at & 3) * 8;
    const bf16* Asel = (tid < 128) ? Ab : As2;
    bf16* AsmSel = (tid < 128) ? As_b : As_s;
    // B: 256x32 per tensor = 1024 cp16; 4 per thread per tensor
    auto load_st = [&](int k0, int st) {
        cp16(AsmSel + st * LG_ATS + ar * APITCH + ak,
             Asel + (size_t)(m0 + ar) * K + k0 + ak);
#pragma unroll
        for (int i = 0; i < 4; i++) {
            int idx = tid + i * 256;
            int br = idx >> 2, bk = (idx & 3) * 8;
            size_t bi = (size_t)br * K + k0 + bk;
            int so = st * LG_BTS + br * APITCH + bk;
            cp16(Bs_b + so, Bb + bi);
            cp16(Bs_s + so, Bs2 + bi);
        }
    };

    const int KT = K >> 5;
    load_st(0, 0);
    CP_COMMIT();

    for (int kt = 0; kt < KT; kt++) {
        if (kt + 1 < KT) {
            load_st((kt + 1) * 32, (kt + 1) & 1);
            CP_COMMIT();
            asm volatile("cp.async.wait_group 1;");
        } else {
            CP_COMMIT();
            asm volatile("cp.async.wait_group 0;");
        }
        __syncthreads();
        const int buf = kt & 1;
        const bf16* ab_base = As_b + buf * LG_ATS;
        const bf16* as_base = As_s + buf * LG_ATS;
        const bf16* bb_base = Bs_b + buf * LG_BTS;
        const bf16* bs_base = Bs_s + buf * LG_BTS;
#pragma unroll
        for (int kk = 0; kk < 32; kk += 16) {
            unsigned ab[4], as_[4], bb[8][2], bs_[8][2];
            ldsm_x4(ab[0], ab[1], ab[2], ab[3], ab_base + arow * APITCH + kk + acolsel);
            ldsm_x4(as_[0], as_[1], as_[2], as_[3], as_base + arow * APITCH + kk + acolsel);
#pragma unroll
            for (int p = 0; p < 4; p++) {
                ldsm_x4(bb[2 * p][0], bb[2 * p][1], bb[2 * p + 1][0], bb[2 * p + 1][1],
                        bb_base + (wn * 64 + p * 16 + brow) * APITCH + kk + bcolsel);
                ldsm_x4(bs_[2 * p][0], bs_[2 * p][1], bs_[2 * p + 1][0], bs_[2 * p + 1][1],
                        bs_base + (wn * 64 + p * 16 + brow) * APITCH + kk + bcolsel);
            }
#pragma unroll
            for (int an = 0; an < 8; an++) {
                mma16816(acc[an], ab, bb[an]);
                mma16816(acc[an], ab, bs_[an]);
                mma16816(acc[an], as_, bb[an]);
            }
        }
        __syncthreads();
    }

    // ---------------- fused residual + LN epilogue ----------------
    float psum[2] = {0.f, 0.f}, psq[2] = {0.f, 0.f};
#pragma unroll
    for (int rr = 0; rr < 2; rr++) {
        int row = m0 + wm * 16 + g + rr * 8;
#pragma unroll
        for (int an = 0; an < 8; an++) {
            int col = wn * 64 + an * 8 + 2 * tig;
#pragma unroll
            for (int cc = 0; cc < 2; cc++) {
                float v = acc[an][rr * 2 + cc] + bias[col + cc] +
                          xres[(size_t)row * C + col + cc];
                acc[an][rr * 2 + cc] = v;
                psum[rr] += v;
                psq[rr] += v * v;
            }
        }
    }
#pragma unroll
    for (int rr = 0; rr < 2; rr++) {
        psum[rr] += __shfl_xor_sync(qm, psum[rr], 1);
        psum[rr] += __shfl_xor_sync(qm, psum[rr], 2);
        psq[rr] += __shfl_xor_sync(qm, psq[rr], 1);
        psq[rr] += __shfl_xor_sync(qm, psq[rr], 2);
        if (tig == 0) {
            int rl = wm * 16 + g + rr * 8;
            red_s[wn][rl] = psum[rr];
            red_q[wn][rl] = psq[rr];
        }
    }
    __syncthreads();
#pragma unroll
    for (int rr = 0; rr < 2; rr++) {
        int rl = wm * 16 + g + rr * 8;
        int row = m0 + rl;
        float s = red_s[0][rl] + red_s[1][rl] + red_s[2][rl] + red_s[3][rl];
        float q = red_q[0][rl] + red_q[1][rl] + red_q[2][rl] + red_q[3][rl];
        float mean = s * (1.0f / C);
        float var = q * (1.0f / C) - mean * mean;
        float rstd = rsqrtf(var + 1e-5f);
        float zero = 1.0f;
        if (apply_mask) {
            int b = row >> 10, t = row & (T - 1);
            if (t >= lens[b]) zero = 0.0f;
        }
#pragma unroll
        for (int an = 0; an < 8; an++) {
            int col = wn * 64 + an * 8 + 2 * tig;
            float y0 = ((acc[an][rr * 2 + 0] - mean) * rstd * gamma[col] + beta[col]) * zero;
            float y1 = ((acc[an][rr * 2 + 1] - mean) * rstd * gamma[col + 1] + beta[col + 1]) * zero;
            size_t o = (size_t)row * C + col;
            xres[o] = y0;
            xres[o + 1] = y1;
            unsigned ub, us;
            cvt2(y0, y1, ub, us);
            *reinterpret_cast<unsigned*>(&outb[o]) = ub;
            *reinterpret_cast<unsigned*>(&outs[o]) = us;
        }
    }
}

// =====================================================================
//  Flash attention: 3-stage cp.async K/V, V row-major + ldsm.trans
// =====================================================================
constexpr int QPITCH = 72;
constexpr int KVT = 64 * QPITCH;
constexpr int FLASH_SMEM = (2 * 128 * QPITCH + 12 * KVT) * (int)sizeof(bf16);  // 147456

__global__ __launch_bounds__(256, 1) void flash_attn(
    const int* __restrict__ lens, const float* __restrict__ relk,
    const float* __restrict__ relv) {
    extern __shared__ bf16 fsm[];
    bf16* Qb = fsm;
    bf16* Qs = fsm + 9216;
    bf16* Ktb = fsm + 18432;
    bf16* Kts = fsm + 18432 + 3 * KVT;
    bf16* Vtb = fsm + 18432 + 6 * KVT;
    bf16* Vts = fsm + 18432 + 9 * KVT;
    __shared__ float qrel_s[128 * NREL];
    __shared__ float relk_s[NREL * HD];
    __shared__ float relv_s[NREL * HD];

    const int tid = threadIdx.x, lane = tid & 31, w = tid >> 5;
    const int g = lane >> 2, tig = lane & 3;
    const unsigned qm = 0xFu << (lane & 28);
    const int m0 = blockIdx.x * 128;
    const int bh = blockIdx.y, b = bh >> 2, h = bh & 3;
    const int len = lens[b];
    const int nt = (len + 63) >> 6;

    const int kr = tid >> 2, cq = (tid & 3) * 16;
    auto load_kv = [&](int k0, int st) {
        size_t gi = ((size_t)(b * T + k0 + kr)) * C + h * HD + cq;
        int so = st * KVT + kr * QPITCH + cq;
        cp16(Ktb + so, g_kb + gi);
        cp16(Ktb + so + 8, g_kb + gi + 8);
        cp16(Kts + so, g_ks + gi);
        cp16(Kts + so + 8, g_ks + gi + 8);
        cp16(Vtb + so, g_vb + gi);
        cp16(Vtb + so + 8, g_vb + gi + 8);
        cp16(Vts + so, g_vs + gi);
        cp16(Vts + so + 8, g_vs + gi + 8);
    };

    load_kv(0, 0);
    CP_COMMIT();
    if (nt > 1) load_kv(64, 1);
    CP_COMMIT();

    {
        int row = tid >> 1, half = (tid & 1) * 32;
        const uint2* sb = (const uint2*)(g_qb + ((size_t)(b * T + m0 + row)) * C + h * HD + half);
        const uint2* ss = (const uint2*)(g_qs + ((size_t)(b * T + m0 + row)) * C + h * HD + half);
        uint2* db = (uint2*)(Qb + row * QPITCH + half);
        uint2* ds = (uint2*)(Qs + row * QPITCH + half);
#pragma unroll
        for (int i = 0; i < 8; i++) { db[i] = sb[i]; ds[i] = ss[i]; }
    }
    for (int i = tid; i < NREL * HD; i += 256) { relk_s[i] = relk[i]; relv_s[i] = relv[i]; }
    __syncthreads();

    for (int i = tid; i < 128 * NREL; i += 256) {
        int r = i / NREL, d = i % NREL;
        const bf16* qb = Qb + r * QPITCH;
        const bf16* qs = Qs + r * QPITCH;
        float s = 0.f;
#pragma unroll
        for (int c = 0; c < HD; c++)
            s += (__bfloat162float(qb[c]) + __bfloat162float(qs[c])) * relk_s[d * HD + c];
        qrel_s[i] = s;
    }

    const int arow = w * 16 + (lane & 7) + ((lane & 8) ? 8 : 0);
    const int acolsel = (lane & 16) ? 8 : 0;
    const int brow = (lane & 7) + ((lane & 16) ? 8 : 0);
    const int bcolsel = (lane & 8) ? 8 : 0;
    const int vrow = (lane & 7) + ((lane & 8) ? 8 : 0);
    const int vcol = (lane & 16) ? 8 : 0;
    unsigned qfb[4][4], qfs[4][4];
#pragma unroll
    for (int s2 = 0; s2 < 4; s2++) {
        ldsm_x4(qfb[s2][0], qfb[s2][1], qfb[s2][2], qfb[s2][3],
                Qb + arow * QPITCH + s2 * 16 + acolsel);
        ldsm_x4(qfs[s2][0], qfs[s2][1], qfs[s2][2], qfs[s2][3],
                Qs + arow * QPITCH + s2 * 16 + acolsel);
    }

    float oacc[8][4] = {};
    float mrow[2] = {-1e30f, -1e30f}, lrow[2] = {0.f, 0.f};

    for (int it = 0; it < nt; it++) {
        const int k0 = it * 64;
        asm volatile("cp.async.wait_group 1;");
        __syncthreads();
        if (it + 2 < nt) load_kv((it + 2) * 64, (it + 2) % 3);
        CP_COMMIT();
        const int st = it % 3;

        float sacc[8][4] = {};
#pragma unroll
        for (int s2 = 0; s2 < 4; s2++) {
            unsigned kb[8][2], km[8][2];
#pragma unroll
            for (int p = 0; p < 4; p++) {
                ldsm_x4(kb[2 * p][0], kb[2 * p][1], kb[2 * p + 1][0], kb[2 * p + 1][1],
                        Ktb + st * KVT + (p * 16 + brow) * QPITCH + s2 * 16 + bcolsel);
                ldsm_x4(km[2 * p][0], km[2 * p][1], km[2 * p + 1][0], km[2 * p + 1][1],
                        Kts + st * KVT + (p * 16 + brow) * QPITCH + s2 * 16 + bcolsel);
            }
#pragma unroll
            for (int an = 0; an < 8; an++) {
                mma16816(sacc[an], qfb[s2], kb[an]);
                mma16816(sacc[an], qfb[s2], km[an]);
                mma16816(sacc[an], qfs[s2], kb[an]);
            }
        }

#pragma unroll
        for (int rr = 0; rr < 2; rr++) {
            int lr = w * 16 + g + rr * 8;
            int qg = m0 + lr;
#pragma unroll
            for (int an = 0; an < 8; an++) {
#pragma unroll
                for (int cc = 0; cc < 2; cc++) {
                    int col = k0 + an * 8 + 2 * tig + cc;
                    float s = sacc[an][rr * 2 + cc];
                    int d = col - qg;
                    if (d >= -4 && d <= 4) s += qrel_s[lr * NREL + d + 4];
                    if (col >= len) s = -1e30f;
                    sacc[an][rr * 2 + cc] = s;
                }
            }
        }

#pragma unroll
        for (int rr = 0; rr < 2; rr++) {
            float mx = -1e30f;
#pragma unroll
            for (int an = 0; an < 8; an++) {
                mx = fmaxf(mx, sacc[an][rr * 2 + 0]);
                mx = fmaxf(mx, sacc[an][rr * 2 + 1]);
            }
            mx = fmaxf(mx, __shfl_xor_sync(qm, mx, 1));
            mx = fmaxf(mx, __shfl_xor_sync(qm, mx, 2));
            float mnew = fmaxf(mrow[rr], mx);
            float corr = __expf(mrow[rr] - mnew);
            mrow[rr] = mnew;
            float rs = 0.f;
#pragma unroll
            for (int an = 0; an < 8; an++) {
#pragma unroll
                for (int cc = 0; cc < 2; cc++) {
                    float p = __expf(sacc[an][rr * 2 + cc] - mnew);
                    sacc[an][rr * 2 + cc] = p;
                    rs += p;
                }
            }
            lrow[rr] = lrow[rr] * corr + rs;
#pragma unroll
            for (int an = 0; an < 8; an++) {
                oacc[an][rr * 2 + 0] *= corr;
                oacc[an][rr * 2 + 1] *= corr;
            }
        }

        unsigned pfb[4][4], pfs[4][4];
#pragma unroll
        for (int s2 = 0; s2 < 4; s2++) {
            cvt2(sacc[2 * s2][0], sacc[2 * s2][1], pfb[s2][0], pfs[s2][0]);
            cvt2(sacc[2 * s2][2], sacc[2 * s2][3], pfb[s2][1], pfs[s2][1]);
            cvt2(sacc[2 * s2 + 1][0], sacc[2 * s2 + 1][1], pfb[s2][2], pfs[s2][2]);
            cvt2(sacc[2 * s2 + 1][2], sacc[2 * s2 + 1][3], pfb[s2][3], pfs[s2][3]);
        }

#pragma unroll
        for (int s2 = 0; s2 < 4; s2++) {
            unsigned vb[8][2], vs2[8][2];
#pragma unroll
            for (int p = 0; p < 4; p++) {
                ldsm_x4_t(vb[2 * p][0], vb[2 * p][1], vb[2 * p + 1][0], vb[2 * p + 1][1],
                          Vtb + st * KVT + (s2 * 16 + vrow) * QPITCH + p * 16 + vcol);
                ldsm_x4_t(vs2[2 * p][0], vs2[2 * p][1], vs2[2 * p + 1][0], vs2[2 * p + 1][1],
                          Vts + st * KVT + (s2 * 16 + vrow) * QPITCH + p * 16 + vcol);
            }
#pragma unroll
            for (int an = 0; an < 8; an++) {
                mma16816(oacc[an], pfb[s2], vb[an]);
                mma16816(oacc[an], pfb[s2], vs2[an]);
                mma16816(oacc[an], pfs[s2], vb[an]);
            }
        }
    }

    float linv[2];
#pragma unroll
    for (int rr = 0; rr < 2; rr++) {
        float lv = lrow[rr];
        lv += __shfl_xor_sync(qm, lv, 1);
        lv += __shfl_xor_sync(qm, lv, 2);
        linv[rr] = 1.0f / lv;
#pragma unroll
        for (int an = 0; an < 8; an++) {
            oacc[an][rr * 2 + 0] *= linv[rr];
            oacc[an][rr * 2 + 1] *= linv[rr];
        }
    }

#pragma unroll
    for (int rr = 0; rr < 2; rr++) {
        int lr = w * 16 + g + rr * 8;
        int qg = m0 + lr;
#pragma unroll
        for (int j = 0; j < NREL; j++) {
            int k = qg + j - 4;
            if (k < 0 || k >= len) continue;
            const bf16* kbp = g_kb + ((size_t)(b * T + k)) * C + h * HD;
            const bf16* ksp = g_ks + ((size_t)(b * T + k)) * C + h * HD;
            float part = 0.f;
#pragma unroll
            for (int c = tig * 16; c < tig * 16 + 16; c++) {
                float qv = __bfloat162float(Qb[lr * QPITCH + c]) +
                           __bfloat162float(Qs[lr * QPITCH + c]);
                float kv = __bfloat162float(kbp[c]) + __bfloat162float(ksp[c]);
                part += qv * kv;
            }
            part += __shfl_xor_sync(qm, part, 1);
            part += __shfl_xor_sync(qm, part, 2);
            float p = __expf(part + qrel_s[lr * NREL + j] - mrow[rr]) * linv[rr];
#pragma unroll
            for (int an = 0; an < 8; an++) {
                int c0 = an * 8 + 2 * tig;
                oacc[an][rr * 2 + 0] += p * relv_s[j * HD + c0];
                oacc[an][rr * 2 + 1] += p * relv_s[j * HD + c0 + 1];
            }
        }
#pragma unroll
        for (int an = 0; an < 8; an++) {
            int c0 = an * 8 + 2 * tig;
            unsigned ub, us;
            cvt2(oacc[an][rr * 2 + 0], oacc[an][rr * 2 + 1], ub, us);
            size_t o = ((size_t)(b * T + qg)) * C + h * HD + c0;
            *reinterpret_cast<unsigned*>(&g_ab[o]) = ub;
            *reinterpret_cast<unsigned*>(&g_as[o]) = us;
        }
    }
}

// ---------------- x (B,T,C) -> out (B,C,T) ----------------
__global__ void transpose_kernel(const float* __restrict__ x, float* __restrict__ out) {
    __shared__ float tile[32][33];
    int b = blockIdx.z;
    int t0 = blockIdx.x * 32, c0 = blockIdx.y * 32;
    int tx = threadIdx.x, ty = threadIdx.y;
#pragma unroll
    for (int i = 0; i < 32; i += 8)
        tile[ty + i][tx] = x[(size_t)(b * T + t0 + ty + i) * C + c0 + tx];
    __syncthreads();
#pragma unroll
    for (int i = 0; i < 32; i += 8)
        out[(size_t)(b * C + c0 + ty + i) * T + t0 + tx] = tile[tx][ty + i];
}

__global__ void mask_out_kernel(const int* __restrict__ lens, float* __restrict__ out_mask) {
    int b = blockIdx.x;
    int len = lens[b];
    for (int t = threadIdx.x; t < T; t += blockDim.x)
        out_mask[(size_t)b * T + t] = (t < len) ? 1.0f : 0.0f;
}

}  // namespace

extern "C" void kernel_launch(void* const* d_in, const int* in_sizes, int n_in,
                              void* d_out, int out_size) {
    (void)in_sizes; (void)n_in; (void)out_size;
    const float* emb   = (const float*)d_in[0];
    const float* Wq    = (const float*)d_in[1];
    const float* Wk    = (const float*)d_in[2];
    const float* Wv    = (const float*)d_in[3];
    const float* Wo    = (const float*)d_in[4];
    const float* bq    = (const float*)d_in[5];
    const float* bk    = (const float*)d_in[6];
    const float* bv    = (const float*)d_in[7];
    const float* bo    = (const float*)d_in[8];
    const float* rel_k = (const float*)d_in[9];
    const float* rel_v = (const float*)d_in[10];
    const float* ln1_g = (const float*)d_in[11];
    const float* ln1_b = (const float*)d_in[12];
    const float* ln2_g = (const float*)d_in[13];
    const float* ln2_b = (const float*)d_in[14];
    const float* fw1   = (const float*)d_in[15];
    const float* fb1   = (const float*)d_in[16];
    const float* fw2   = (const float*)d_in[17];
    const float* fb2   = (const float*)d_in[18];
    const float* pw    = (const float*)d_in[19];
    const float* pb    = (const float*)d_in[20];
    const int*   toks  = (const int*)d_in[21];
    const int*   lens  = (const int*)d_in[22];

    cudaFuncSetAttribute(mma_gemm_p<0>, cudaFuncAttributeMaxDynamicSharedMemorySize, SMEM_BYTES);
    cudaFuncSetAttribute(mma_gemm_p<1>, cudaFuncAttributeMaxDynamicSharedMemorySize, SMEM_BYTES);
    cudaFuncSetAttribute(mma_gemm_p<3>, cudaFuncAttributeMaxDynamicSharedMemorySize, SMEM_BYTES);
    cudaFuncSetAttribute(ln_gemm, cudaFuncAttributeMaxDynamicSharedMemorySize, LG_SMEM);
    cudaFuncSetAttribute(flash_attn, cudaFuncAttributeMaxDynamicSharedMemorySize, FLASH_SMEM);

    float* px;
    bf16 *pwb, *pws, *pxb, *pxs, *pab, *pas, *pfb, *pfs;
    cudaGetSymbolAddress((void**)&px,   g_x);
    cudaGetSymbolAddress((void**)&pwb,  g_wb);
    cudaGetSymbolAddress((void**)&pws,  g_ws);
    cudaGetSymbolAddress((void**)&pxb,  g_xb);
    cudaGetSymbolAddress((void**)&pxs,  g_xs);
    cudaGetSymbolAddress((void**)&pab,  g_ab);
    cudaGetSymbolAddress((void**)&pas,  g_as);
    cudaGetSymbolAddress((void**)&pfb,  g_fb);
    cudaGetSymbolAddress((void**)&pfs,  g_fs);

    float* out      = (float*)d_out;
    float* out_x    = out;
    float* out_m    = out + (size_t)B * C * T;
    float* out_logs = out_m + (size_t)B * OUT * T;
    float* out_mask = out_logs + (size_t)B * OUT * T;

    prep_kernel<<<6016, 256>>>(Wq, Wk, Wv, Wo, fw1, fw2, pw, emb, toks);

    dim3 gQKV(3 * C / 128, BT / 128);
    dim3 gFC(FC / 128, BT / 128);

    for (int l = 0; l < L; l++) {
        size_t qkv = OFF_QKV + (size_t)l * 3 * C * C;
        size_t wo = OFF_WO + (size_t)l * C * C;
        size_t f1 = OFF_F1 + (size_t)l * C * FC;
        size_t f2 = OFF_F2 + (size_t)l * FC * C;

        mma_gemm_p<1><<<gQKV, 256, SMEM_BYTES>>>(
            pxb, pxs, pwb + qkv, pws + qkv, bq + (size_t)l * C, bk + (size_t)l * C,
            bv + (size_t)l * C, nullptr, nullptr, nullptr, nullptr, BT, 3 * C, C, 1.0f, 0,
            nullptr);

        flash_attn<<<dim3(T / 128, B * H), 256, FLASH_SMEM>>>(
            lens, rel_k + (size_t)l * NREL * HD, rel_v + (size_t)l * NREL * HD);

        // Wo GEMM + residual + LN1 fused
        ln_gemm<<<BT / 32, 256, LG_SMEM>>>(pab, pas, pwb + wo, pws + wo, bo + (size_t)l * C,
                                           ln1_g + (size_t)l * C, ln1_b + (size_t)l * C, px,
                                           pxb, pxs, C, 0, lens);

        mma_gemm_p<0><<<gFC, 256, SMEM_BYTES>>>(pxb, pxs, pwb + f1, pws + f1,
                                                fb1 + (size_t)l * FC, nullptr, nullptr, nullptr,
                                                pfb, pfs, nullptr, BT, FC, C, 1.0f, 1, nullptr);

        // FFN2 GEMM + residual + LN2 + mask fused
        ln_gemm<<<BT / 32, 256, LG_SMEM>>>(pfb, pfs, pwb + f2, pws + f2, fb2 + (size_t)l * C,
                                           ln2_g + (size_t)l * C, ln2_b + (size_t)l * C, px,
                                           pxb, pxs, FC, 1, lens);
    }

    transpose_kernel<<<dim3(T / 32, C / 32, B), dim3(32, 8)>>>(px, out_x);
    mma_gemm_p<3><<<dim3(2 * OUT / 128, BT / 128), 256, SMEM_BYTES>>>(
        pxb, pxs, pwb + OFF_PJ, pws + OFF_PJ, pb, nullptr, nullptr, out_m, nullptr, nullptr,
        out_logs, BT, 2 * OUT, C, 1.0f, 0, lens);
    mask_out_kernel<<<B, 256>>>(lens, out_mask);
}

// round 16
// speedup vs baseline: 1.0315x; 1.0315x over previous
#include <cuda_runtime.h>
#include <cuda_bf16.h>
#include <math.h>

namespace {

constexpr int C = 256, H = 4, HD = 64, L = 6, FC = 1024, OUT = 192;
constexpr int B = 8, T = 1024, BT = B * T, NREL = 9;

typedef __nv_bfloat16 bf16;

// ---------------- weight pair storage (QKV concatenated per layer) ----------------
constexpr size_t OFF_QKV = 0;
constexpr size_t OFF_WO  = (size_t)L * 3 * C * C;
constexpr size_t OFF_F1  = OFF_WO + (size_t)L * C * C;
constexpr size_t OFF_F2  = OFF_F1 + (size_t)L * C * FC;
constexpr size_t OFF_PJ  = OFF_F2 + (size_t)L * FC * C;
constexpr size_t WTOT    = OFF_PJ + (size_t)2 * OUT * C;

__device__ bf16 g_wb[WTOT];
__device__ bf16 g_ws[WTOT];

// ---------------- activation scratch ----------------
__device__ float g_x[BT * C];
__device__ float g_tmp[BT * C];
__device__ bf16 g_xb[BT * C], g_xs[BT * C];
__device__ bf16 g_qb[BT * C], g_qs[BT * C];
__device__ bf16 g_kb[BT * C], g_ks[BT * C];
__device__ bf16 g_vb[BT * C], g_vs[BT * C];
__device__ bf16 g_ab[BT * C], g_as[BT * C];
__device__ bf16 g_fb[BT * FC], g_fs[BT * FC];

// ---------------- helpers ----------------
__device__ __forceinline__ float warpReduceSum(float v) {
#pragma unroll
    for (int o = 16; o; o >>= 1) v += __shfl_xor_sync(0xffffffffu, v, o);
    return v;
}

__device__ __forceinline__ void cvt2(float a, float b, unsigned& ub, unsigned& us) {
    __nv_bfloat162 hb, hs;
    hb.x = __float2bfloat16_rn(a);
    hb.y = __float2bfloat16_rn(b);
    float ra = a - __bfloat162float(hb.x);
    float rb = b - __bfloat162float(hb.y);
    hs.x = __float2bfloat16_rn(ra);
    hs.y = __float2bfloat16_rn(rb);
    ub = *reinterpret_cast<unsigned*>(&hb);
    us = *reinterpret_cast<unsigned*>(&hs);
}

__device__ __forceinline__ void mma16816(float c[4], const unsigned a[4], const unsigned b2[2]) {
    asm volatile(
        "mma.sync.aligned.m16n8k16.row.col.f32.bf16.bf16.f32 "
        "{%0,%1,%2,%3}, {%4,%5,%6,%7}, {%8,%9}, {%0,%1,%2,%3};\n"
        : "+f"(c[0]), "+f"(c[1]), "+f"(c[2]), "+f"(c[3])
        : "r"(a[0]), "r"(a[1]), "r"(a[2]), "r"(a[3]), "r"(b2[0]), "r"(b2[1]));
}

__device__ __forceinline__ void ldsm_x4(unsigned& r0, unsigned& r1, unsigned& r2, unsigned& r3,
                                        const void* p) {
    unsigned addr = (unsigned)__cvta_generic_to_shared(p);
    asm volatile("ldmatrix.sync.aligned.m8n8.x4.shared.b16 {%0,%1,%2,%3}, [%4];"
                 : "=r"(r0), "=r"(r1), "=r"(r2), "=r"(r3)
                 : "r"(addr));
}
__device__ __forceinline__ void ldsm_x4_t(unsigned& r0, unsigned& r1, unsigned& r2, unsigned& r3,
                                          const void* p) {
    unsigned addr = (unsigned)__cvta_generic_to_shared(p);
    asm volatile("ldmatrix.sync.aligned.m8n8.x4.trans.shared.b16 {%0,%1,%2,%3}, [%4];"
                 : "=r"(r0), "=r"(r1), "=r"(r2), "=r"(r3)
                 : "r"(addr));
}
__device__ __forceinline__ void cp16(void* s, const void* g) {
    unsigned a = (unsigned)__cvta_generic_to_shared(s);
    asm volatile("cp.async.cg.shared.global [%0], [%1], 16;" :: "r"(a), "l"(g));
}
#define CP_COMMIT() asm volatile("cp.async.commit_group;")

// =====================================================================
//  prep kernel
// =====================================================================
__device__ void wconv_blk(const float* __restrict__ w, bf16* __restrict__ ob,
                          bf16* __restrict__ os, int K, int N, size_t lstride, int bx) {
    __shared__ float tile[32][33];
    int nx = N / 32, ny = K / 32;
    int l = bx / (nx * ny);
    int rem = bx % (nx * ny);
    int y = rem / nx, x = rem % nx;
    const float* src = w + (size_t)l * K * N;
    int k0 = y * 32, n0 = x * 32;
    int tx = threadIdx.x & 31, ty = threadIdx.x >> 5;
#pragma unroll
    for (int i = 0; i < 32; i += 8)
        tile[ty + i][tx] = src[(size_t)(k0 + ty + i) * N + n0 + tx];
    __syncthreads();
#pragma unroll
    for (int i = 0; i < 32; i += 8) {
        float v = tile[tx][ty + i];
        size_t o = (size_t)l * lstride + (size_t)(n0 + ty + i) * K + k0 + tx;
        bf16 hb = __float2bfloat16_rn(v);
        ob[o] = hb;
        os[o] = __float2bfloat16_rn(v - __bfloat162float(hb));
    }
}

__global__ void prep_kernel(const float* __restrict__ Wq, const float* __restrict__ Wk,
                            const float* __restrict__ Wv, const float* __restrict__ Wo,
                            const float* __restrict__ fw1, const float* __restrict__ fw2,
                            const float* __restrict__ pw, const float* __restrict__ emb,
                            const int* __restrict__ toks) {
    int bx = blockIdx.x;
    if (bx < 384) { wconv_blk(Wq, g_wb + OFF_QKV, g_ws + OFF_QKV, C, C, (size_t)3 * C * C, bx); return; }
    bx -= 384;
    if (bx < 384) { wconv_blk(Wk, g_wb + OFF_QKV + C * C, g_ws + OFF_QKV + C * C, C, C, (size_t)3 * C * C, bx); return; }
    bx -= 384;
    if (bx < 384) { wconv_blk(Wv, g_wb + OFF_QKV + 2 * C * C, g_ws + OFF_QKV + 2 * C * C, C, C, (size_t)3 * C * C, bx); return; }
    bx -= 384;
    if (bx < 384) { wconv_blk(Wo, g_wb + OFF_WO, g_ws + OFF_WO, C, C, (size_t)C * C, bx); return; }
    bx -= 384;
    if (bx < 1536) { wconv_blk(fw1, g_wb + OFF_F1, g_ws + OFF_F1, C, FC, (size_t)C * FC, bx); return; }
    bx -= 1536;
    if (bx < 1536) { wconv_blk(fw2, g_wb + OFF_F2, g_ws + OFF_F2, FC, C, (size_t)FC * C, bx); return; }
    bx -= 1536;
    if (bx < 384) {
        int i = bx * 256 + threadIdx.x;
        if (i < 2 * OUT * C) {
            float v = pw[i];
            bf16 hb = __float2bfloat16_rn(v);
            g_wb[OFF_PJ + i] = hb;
            g_ws[OFF_PJ + i] = __float2bfloat16_rn(v - __bfloat162float(hb));
        }
        return;
    }
    bx -= 384;
#pragma unroll
    for (int j = 0; j < 8; j++) {
        int idx = bx * 2048 + j * 256 + threadIdx.x;
        int bt = idx >> 8, c = idx & 255;
        float v = emb[(size_t)toks[bt] * C + c] * 16.0f;
        g_x[idx] = v;
        bf16 hb = __float2bfloat16_rn(v);
        g_xb[idx] = hb;
        g_xs[idx] = __float2bfloat16_rn(v - __bfloat162float(hb));
    }
}

// =====================================================================
//  Pair-input bf16x3 GEMM: 128x128 tile (QKV / FFN1 / stats)
// =====================================================================
constexpr int APITCH = 40;
constexpr int TSZ = 128 * APITCH;
constexpr int SMEM_BYTES = 8 * TSZ * (int)sizeof(bf16);  // 81920

template <int MODE>
__global__ __launch_bounds__(256, 2) void mma_gemm_p(
    const bf16* __restrict__ Ab, const bf16* __restrict__ As2,
    const bf16* __restrict__ Bb, const bf16* __restrict__ Bs2,
    const float* __restrict__ bias, const float* __restrict__ bias2,
    const float* __restrict__ bias3, float* __restrict__ outf,
    bf16* __restrict__ outb, bf16* __restrict__ outs, float* __restrict__ out2,
    int M, int N, int K, float alpha, int relu, const int* __restrict__ lens) {
    extern __shared__ bf16 dsm[];
    bf16* As_b = dsm;
    bf16* As_s = dsm + 2 * TSZ;
    bf16* Bs_b = dsm + 4 * TSZ;
    bf16* Bs_s = dsm + 6 * TSZ;

    const int tid = threadIdx.x;
    const int lane = tid & 31, wid = tid >> 5;
    const int wm = wid >> 1, wn = wid & 1;
    const int g = lane >> 2, tig = lane & 3;
    const int m0 = blockIdx.y * 128, n0 = blockIdx.x * 128;

    const int ar = tid >> 1, akh = (tid & 1) * 16;

    const int lane7 = lane & 7;
    const int arow = wm * 32 + lane7 + ((lane & 8) ? 8 : 0);
    const int acolsel = (lane & 16) ? 8 : 0;
    const int brow = lane7 + ((lane & 16) ? 8 : 0);
    const int bcolsel = (lane & 8) ? 8 : 0;

    float acc[2][8][4] = {};

    auto load_st = [&](int k0, int st) {
        size_t ai = (size_t)(m0 + ar) * K + k0 + akh;
        size_t bi = (size_t)(n0 + ar) * K + k0 + akh;
        int so = st * TSZ + ar * APITCH + akh;
        cp16(As_b + so, Ab + ai);
        cp16(As_b + so + 8, Ab + ai + 8);
        cp16(As_s + so, As2 + ai);
        cp16(As_s + so + 8, As2 + ai + 8);
        cp16(Bs_b + so, Bb + bi);
        cp16(Bs_b + so + 8, Bb + bi + 8);
        cp16(Bs_s + so, Bs2 + bi);
        cp16(Bs_s + so + 8, Bs2 + bi + 8);
    };

    const int KT = K >> 5;
    load_st(0, 0);
    CP_COMMIT();

    for (int kt = 0; kt < KT; kt++) {
        if (kt + 1 < KT) {
            load_st((kt + 1) * 32, (kt + 1) & 1);
            CP_COMMIT();
            asm volatile("cp.async.wait_group 1;");
        } else {
            CP_COMMIT();
            asm volatile("cp.async.wait_group 0;");
        }
        __syncthreads();
        const int buf = kt & 1;
        const bf16* ab_base = As_b + buf * TSZ;
        const bf16* as_base = As_s + buf * TSZ;
        const bf16* bb_base = Bs_b + buf * TSZ;
        const bf16* bs_base = Bs_s + buf * TSZ;
#pragma unroll
        for (int kk = 0; kk < 32; kk += 16) {
            unsigned ab[2][4], as_[2][4], bb[8][2], bs_[8][2];
#pragma unroll
            for (int am = 0; am < 2; am++) {
                ldsm_x4(ab[am][0], ab[am][1], ab[am][2], ab[am][3],
                        ab_base + (arow + am * 16) * APITCH + kk + acolsel);
                ldsm_x4(as_[am][0], as_[am][1], as_[am][2], as_[am][3],
                        as_base + (arow + am * 16) * APITCH + kk + acolsel);
            }
#pragma unroll
            for (int p = 0; p < 4; p++) {
                ldsm_x4(bb[2 * p][0], bb[2 * p][1], bb[2 * p + 1][0], bb[2 * p + 1][1],
                        bb_base + (wn * 64 + p * 16 + brow) * APITCH + kk + bcolsel);
                ldsm_x4(bs_[2 * p][0], bs_[2 * p][1], bs_[2 * p + 1][0], bs_[2 * p + 1][1],
                        bs_base + (wn * 64 + p * 16 + brow) * APITCH + kk + bcolsel);
            }
#pragma unroll
            for (int am = 0; am < 2; am++)
#pragma unroll
                for (int an = 0; an < 8; an++) {
                    mma16816(acc[am][an], ab[am], bb[an]);
                    mma16816(acc[am][an], ab[am], bs_[an]);
                    mma16816(acc[am][an], as_[am], bb[an]);
                }
        }
        __syncthreads();
    }

    // ---------------- epilogue ----------------
    int tgt = 0;
    const float* biasp = bias;
    bf16* tob = outb;
    bf16* tos = outs;
    float al = alpha;
    if constexpr (MODE == 1) {
        tgt = n0 >> 8;
        biasp = (tgt == 0) ? bias : (tgt == 1 ? bias2 : bias3);
        tob = (tgt == 0) ? g_qb : (tgt == 1 ? g_kb : g_vb);
        tos = (tgt == 0) ? g_qs : (tgt == 1 ? g_ks : g_vs);
        al = (tgt == 0) ? 0.125f : 1.0f;
    }

#pragma unroll
    for (int am = 0; am < 2; am++) {
#pragma unroll
        for (int rr = 0; rr < 2; rr++) {
            int row = m0 + wm * 32 + am * 16 + g + rr * 8;
#pragma unroll
            for (int an = 0; an < 8; an++) {
                int col0 = n0 + wn * 64 + an * 8 + 2 * tig;
                if constexpr (MODE == 0) {
                    float v0 = (acc[am][an][rr * 2 + 0] + bias[col0]) * alpha;
                    float v1 = (acc[am][an][rr * 2 + 1] + bias[col0 + 1]) * alpha;
                    if (relu) { v0 = fmaxf(v0, 0.f); v1 = fmaxf(v1, 0.f); }
                    if (outf) {
                        outf[(size_t)row * N + col0] = v0;
                        outf[(size_t)row * N + col0 + 1] = v1;
                    }
                    if (outb) {
                        unsigned ub, us;
                        cvt2(v0, v1, ub, us);
                        *reinterpret_cast<unsigned*>(&outb[(size_t)row * N + col0]) = ub;
                        *reinterpret_cast<unsigned*>(&outs[(size_t)row * N + col0]) = us;
                    }
                } else if constexpr (MODE == 1) {
                    int lc = col0 - tgt * 256;
                    float v0 = (acc[am][an][rr * 2 + 0] + biasp[lc]) * al;
                    float v1 = (acc[am][an][rr * 2 + 1] + biasp[lc + 1]) * al;
                    unsigned ub, us;
                    cvt2(v0, v1, ub, us);
                    *reinterpret_cast<unsigned*>(&tob[(size_t)row * C + lc]) = ub;
                    *reinterpret_cast<unsigned*>(&tos[(size_t)row * C + lc]) = us;
                } else {  // MODE 3
                    int bb2 = row >> 10, tt = row & (T - 1);
                    float mk = (tt < lens[bb2]) ? 1.0f : 0.0f;
#pragma unroll
                    for (int cc = 0; cc < 2; cc++) {
                        int col = col0 + cc;
                        float vv = (acc[am][an][rr * 2 + cc] + bias[col]) * mk;
                        if (col < OUT)
                            outf[((size_t)bb2 * OUT + col) * T + tt] = vv;
                        else
                            out2[((size_t)bb2 * OUT + (col - OUT)) * T + tt] = vv;
                    }
                }
            }
        }
    }
}

// =====================================================================
//  64M x 128N tile GEMM for N=256 layers (Wo, FFN2): grid 256 blocks.
//  8 warps as 2M x 4N, warp tile 32x32. fp32 out only.
// =====================================================================
constexpr int G64_ATS = 64 * APITCH;    // 2560
constexpr int G64_BTS = 128 * APITCH;   // 5120
constexpr int G64_SMEM = (4 * G64_ATS + 4 * G64_BTS) * (int)sizeof(bf16);  // 61440

__global__ __launch_bounds__(256, 2) void mma_gemm64(
    const bf16* __restrict__ Ab, const bf16* __restrict__ As2,
    const bf16* __restrict__ Bb, const bf16* __restrict__ Bs2,
    const float* __restrict__ bias, float* __restrict__ outf, int N, int K) {
    extern __shared__ bf16 dsm[];
    bf16* As_b = dsm;                                  // [2][64][40]
    bf16* As_s = dsm + 2 * G64_ATS;
    bf16* Bs_b = dsm + 4 * G64_ATS;                    // [2][128][40]
    bf16* Bs_s = dsm + 4 * G64_ATS + 2 * G64_BTS;

    const int tid = threadIdx.x;
    const int lane = tid & 31, wid = tid >> 5;
    const int wm = wid >> 2, wn = wid & 3;             // 2M x 4N
    const int g = lane >> 2, tig = lane & 3;
    const int m0 = blockIdx.y * 64, n0 = blockIdx.x * 128;

    const int lane7 = lane & 7;
    const int arow = wm * 32 + lane7 + ((lane & 8) ? 8 : 0);
    const int acolsel = (lane & 16) ? 8 : 0;
    const int brow = wn * 32 + lane7 + ((lane & 16) ? 8 : 0);
    const int bcolsel = (lane & 8) ? 8 : 0;

    float acc[2][4][4] = {};

    const int ar = tid >> 2, ak = (tid & 3) * 8;       // A: 64 rows x 32k
    const int br = tid >> 1, bk = (tid & 1) * 16;      // B: 128 rows x 32k

    auto load_st = [&](int k0, int st) {
        size_t ai = (size_t)(m0 + ar) * K + k0 + ak;
        cp16(As_b + st * G64_ATS + ar * APITCH + ak, Ab + ai);
        cp16(As_s + st * G64_ATS + ar * APITCH + ak, As2 + ai);
        size_t bi = (size_t)(n0 + br) * K + k0 + bk;
        int so = st * G64_BTS + br * APITCH + bk;
        cp16(Bs_b + so, Bb + bi);
        cp16(Bs_b + so + 8, Bb + bi + 8);
        cp16(Bs_s + so, Bs2 + bi);
        cp16(Bs_s + so + 8, Bs2 + bi + 8);
    };

    const int KT = K >> 5;
    load_st(0, 0);
    CP_COMMIT();

    for (int kt = 0; kt < KT; kt++) {
        if (kt + 1 < KT) {
            load_st((kt + 1) * 32, (kt + 1) & 1);
            CP_COMMIT();
            asm volatile("cp.async.wait_group 1;");
        } else {
            CP_COMMIT();
            asm volatile("cp.async.wait_group 0;");
        }
        __syncthreads();
        const int buf = kt & 1;
        const bf16* ab_base = As_b + buf * G64_ATS;
        const bf16* as_base = As_s + buf * G64_ATS;
        const bf16* bb_base = Bs_b + buf * G64_BTS;
        const bf16* bs_base = Bs_s + buf * G64_BTS;
#pragma unroll
        for (int kk = 0; kk < 32; kk += 16) {
            unsigned ab[2][4], as_[2][4], bb[4][2], bs_[4][2];
#pragma unroll
            for (int am = 0; am < 2; am++) {
                ldsm_x4(ab[am][0], ab[am][1], ab[am][2], ab[am][3],
                        ab_base + (arow + am * 16) * APITCH + kk + acolsel);
                ldsm_x4(as_[am][0], as_[am][1], as_[am][2], as_[am][3],
                        as_base + (arow + am * 16) * APITCH + kk + acolsel);
            }
#pragma unroll
            for (int p = 0; p < 2; p++) {
                ldsm_x4(bb[2 * p][0], bb[2 * p][1], bb[2 * p + 1][0], bb[2 * p + 1][1],
                        bb_base + (brow + p * 16) * APITCH + kk + bcolsel);
                ldsm_x4(bs_[2 * p][0], bs_[2 * p][1], bs_[2 * p + 1][0], bs_[2 * p + 1][1],
                        bs_base + (brow + p * 16) * APITCH + kk + bcolsel);
            }
#pragma unroll
            for (int am = 0; am < 2; am++)
#pragma unroll
                for (int an = 0; an < 4; an++) {
                    mma16816(acc[am][an], ab[am], bb[an]);
                    mma16816(acc[am][an], ab[am], bs_[an]);
                    mma16816(acc[am][an], as_[am], bb[an]);
                }
        }
        __syncthreads();
    }

#pragma unroll
    for (int am = 0; am < 2; am++) {
#pragma unroll
        for (int rr = 0; rr < 2; rr++) {
            int row = m0 + wm * 32 + am * 16 + g + rr * 8;
#pragma unroll
            for (int an = 0; an < 4; an++) {
                int col = n0 + wn * 32 + an * 8 + 2 * tig;
                float v0 = acc[am][an][rr * 2 + 0] + bias[col];
                float v1 = acc[am][an][rr * 2 + 1] + bias[col + 1];
                outf[(size_t)row * N + col] = v0;
                outf[(size_t)row * N + col + 1] = v1;
            }
        }
    }
}

// =====================================================================
//  Flash attention: 3-stage cp.async K/V, V row-major + ldsm.trans
// =====================================================================
constexpr int QPITCH = 72;
constexpr int KVT = 64 * QPITCH;
constexpr int FLASH_SMEM = (2 * 128 * QPITCH + 12 * KVT) * (int)sizeof(bf16);  // 147456

__global__ __launch_bounds__(256, 1) void flash_attn(
    const int* __restrict__ lens, const float* __restrict__ relk,
    const float* __restrict__ relv) {
    extern __shared__ bf16 fsm[];
    bf16* Qb = fsm;
    bf16* Qs = fsm + 9216;
    bf16* Ktb = fsm + 18432;
    bf16* Kts = fsm + 18432 + 3 * KVT;
    bf16* Vtb = fsm + 18432 + 6 * KVT;
    bf16* Vts = fsm + 18432 + 9 * KVT;
    __shared__ float qrel_s[128 * NREL];
    __shared__ float relk_s[NREL * HD];
    __shared__ float relv_s[NREL * HD];

    const int tid = threadIdx.x, lane = tid & 31, w = tid >> 5;
    const int g = lane >> 2, tig = lane & 3;
    const unsigned qm = 0xFu << (lane & 28);
    const int m0 = blockIdx.x * 128;
    const int bh = blockIdx.y, b = bh >> 2, h = bh & 3;
    const int len = lens[b];
    const int nt = (len + 63) >> 6;

    const int kr = tid >> 2, cq = (tid & 3) * 16;
    auto load_kv = [&](int k0, int st) {
        size_t gi = ((size_t)(b * T + k0 + kr)) * C + h * HD + cq;
        int so = st * KVT + kr * QPITCH + cq;
        cp16(Ktb + so, g_kb + gi);
        cp16(Ktb + so + 8, g_kb + gi + 8);
        cp16(Kts + so, g_ks + gi);
        cp16(Kts + so + 8, g_ks + gi + 8);
        cp16(Vtb + so, g_vb + gi);
        cp16(Vtb + so + 8, g_vb + gi + 8);
        cp16(Vts + so, g_vs + gi);
        cp16(Vts + so + 8, g_vs + gi + 8);
    };

    load_kv(0, 0);
    CP_COMMIT();
    if (nt > 1) load_kv(64, 1);
    CP_COMMIT();

    {
        int row = tid >> 1, half = (tid & 1) * 32;
        const uint2* sb = (const uint2*)(g_qb + ((size_t)(b * T + m0 + row)) * C + h * HD + half);
        const uint2* ss = (const uint2*)(g_qs + ((size_t)(b * T + m0 + row)) * C + h * HD + half);
        uint2* db = (uint2*)(Qb + row * QPITCH + half);
        uint2* ds = (uint2*)(Qs + row * QPITCH + half);
#pragma unroll
        for (int i = 0; i < 8; i++) { db[i] = sb[i]; ds[i] = ss[i]; }
    }
    for (int i = tid; i < NREL * HD; i += 256) { relk_s[i] = relk[i]; relv_s[i] = relv[i]; }
    __syncthreads();

    for (int i = tid; i < 128 * NREL; i += 256) {
        int r = i / NREL, d = i % NREL;
        const bf16* qb = Qb + r * QPITCH;
        const bf16* qs = Qs + r * QPITCH;
        float s = 0.f;
#pragma unroll
        for (int c = 0; c < HD; c++)
            s += (__bfloat162float(qb[c]) + __bfloat162float(qs[c])) * relk_s[d * HD + c];
        qrel_s[i] = s;
    }

    const int arow = w * 16 + (lane & 7) + ((lane & 8) ? 8 : 0);
    const int acolsel = (lane & 16) ? 8 : 0;
    const int brow = (lane & 7) + ((lane & 16) ? 8 : 0);
    const int bcolsel = (lane & 8) ? 8 : 0;
    const int vrow = (lane & 7) + ((lane & 8) ? 8 : 0);
    const int vcol = (lane & 16) ? 8 : 0;
    unsigned qfb[4][4], qfs[4][4];
#pragma unroll
    for (int s2 = 0; s2 < 4; s2++) {
        ldsm_x4(qfb[s2][0], qfb[s2][1], qfb[s2][2], qfb[s2][3],
                Qb + arow * QPITCH + s2 * 16 + acolsel);
        ldsm_x4(qfs[s2][0], qfs[s2][1], qfs[s2][2], qfs[s2][3],
                Qs + arow * QPITCH + s2 * 16 + acolsel);
    }

    float oacc[8][4] = {};
    float mrow[2] = {-1e30f, -1e30f}, lrow[2] = {0.f, 0.f};

    for (int it = 0; it < nt; it++) {
        const int k0 = it * 64;
        asm volatile("cp.async.wait_group 1;");
        __syncthreads();
        if (it + 2 < nt) load_kv((it + 2) * 64, (it + 2) % 3);
        CP_COMMIT();
        const int st = it % 3;

        float sacc[8][4] = {};
#pragma unroll
        for (int s2 = 0; s2 < 4; s2++) {
            unsigned kb[8][2], km[8][2];
#pragma unroll
            for (int p = 0; p < 4; p++) {
                ldsm_x4(kb[2 * p][0], kb[2 * p][1], kb[2 * p + 1][0], kb[2 * p + 1][1],
                        Ktb + st * KVT + (p * 16 + brow) * QPITCH + s2 * 16 + bcolsel);
                ldsm_x4(km[2 * p][0], km[2 * p][1], km[2 * p + 1][0], km[2 * p + 1][1],
                        Kts + st * KVT + (p * 16 + brow) * QPITCH + s2 * 16 + bcolsel);
            }
#pragma unroll
            for (int an = 0; an < 8; an++) {
                mma16816(sacc[an], qfb[s2], kb[an]);
                mma16816(sacc[an], qfb[s2], km[an]);
                mma16816(sacc[an], qfs[s2], kb[an]);
            }
        }

#pragma unroll
        for (int rr = 0; rr < 2; rr++) {
            int lr = w * 16 + g + rr * 8;
            int qg = m0 + lr;
#pragma unroll
            for (int an = 0; an < 8; an++) {
#pragma unroll
                for (int cc = 0; cc < 2; cc++) {
                    int col = k0 + an * 8 + 2 * tig + cc;
                    float s = sacc[an][rr * 2 + cc];
                    int d = col - qg;
                    if (d >= -4 && d <= 4) s += qrel_s[lr * NREL + d + 4];
                    if (col >= len) s = -1e30f;
                    sacc[an][rr * 2 + cc] = s;
                }
            }
        }

#pragma unroll
        for (int rr = 0; rr < 2; rr++) {
            float mx = -1e30f;
#pragma unroll
            for (int an = 0; an < 8; an++) {
                mx = fmaxf(mx, sacc[an][rr * 2 + 0]);
                mx = fmaxf(mx, sacc[an][rr * 2 + 1]);
            }
            mx = fmaxf(mx, __shfl_xor_sync(qm, mx, 1));
            mx = fmaxf(mx, __shfl_xor_sync(qm, mx, 2));
            float mnew = fmaxf(mrow[rr], mx);
            float corr = __expf(mrow[rr] - mnew);
            mrow[rr] = mnew;
            float rs = 0.f;
#pragma unroll
            for (int an = 0; an < 8; an++) {
#pragma unroll
                for (int cc = 0; cc < 2; cc++) {
                    float p = __expf(sacc[an][rr * 2 + cc] - mnew);
                    sacc[an][rr * 2 + cc] = p;
                    rs += p;
                }
            }
            lrow[rr] = lrow[rr] * corr + rs;
#pragma unroll
            for (int an = 0; an < 8; an++) {
                oacc[an][rr * 2 + 0] *= corr;
                oacc[an][rr * 2 + 1] *= corr;
            }
        }

        unsigned pfb[4][4], pfs[4][4];
#pragma unroll
        for (int s2 = 0; s2 < 4; s2++) {
            cvt2(sacc[2 * s2][0], sacc[2 * s2][1], pfb[s2][0], pfs[s2][0]);
            cvt2(sacc[2 * s2][2], sacc[2 * s2][3], pfb[s2][1], pfs[s2][1]);
            cvt2(sacc[2 * s2 + 1][0], sacc[2 * s2 + 1][1], pfb[s2][2], pfs[s2][2]);
            cvt2(sacc[2 * s2 + 1][2], sacc[2 * s2 + 1][3], pfb[s2][3], pfs[s2][3]);
        }

#pragma unroll
        for (int s2 = 0; s2 < 4; s2++) {
            unsigned vb[8][2], vs2[8][2];
#pragma unroll
            for (int p = 0; p < 4; p++) {
                ldsm_x4_t(vb[2 * p][0], vb[2 * p][1], vb[2 * p + 1][0], vb[2 * p + 1][1],
                          Vtb + st * KVT + (s2 * 16 + vrow) * QPITCH + p * 16 + vcol);
                ldsm_x4_t(vs2[2 * p][0], vs2[2 * p][1], vs2[2 * p + 1][0], vs2[2 * p + 1][1],
                          Vts + st * KVT + (s2 * 16 + vrow) * QPITCH + p * 16 + vcol);
            }
#pragma unroll
            for (int an = 0; an < 8; an++) {
                mma16816(oacc[an], pfb[s2], vb[an]);
                mma16816(oacc[an], pfb[s2], vs2[an]);
                mma16816(oacc[an], pfs[s2], vb[an]);
            }
        }
    }

    float linv[2];
#pragma unroll
    for (int rr = 0; rr < 2; rr++) {
        float lv = lrow[rr];
        lv += __shfl_xor_sync(qm, lv, 1);
        lv += __shfl_xor_sync(qm, lv, 2);
        linv[rr] = 1.0f / lv;
#pragma unroll
        for (int an = 0; an < 8; an++) {
            oacc[an][rr * 2 + 0] *= linv[rr];
            oacc[an][rr * 2 + 1] *= linv[rr];
        }
    }

#pragma unroll
    for (int rr = 0; rr < 2; rr++) {
        int lr = w * 16 + g + rr * 8;
        int qg = m0 + lr;
#pragma unroll
        for (int j = 0; j < NREL; j++) {
            int k = qg + j - 4;
            if (k < 0 || k >= len) continue;
            const bf16* kbp = g_kb + ((size_t)(b * T + k)) * C + h * HD;
            const bf16* ksp = g_ks + ((size_t)(b * T + k)) * C + h * HD;
            float part = 0.f;
#pragma unroll
            for (int c = tig * 16; c < tig * 16 + 16; c++) {
                float qv = __bfloat162float(Qb[lr * QPITCH + c]) +
                           __bfloat162float(Qs[lr * QPITCH + c]);
                float kv = __bfloat162float(kbp[c]) + __bfloat162float(ksp[c]);
                part += qv * kv;
            }
            part += __shfl_xor_sync(qm, part, 1);
            part += __shfl_xor_sync(qm, part, 2);
            float p = __expf(part + qrel_s[lr * NREL + j] - mrow[rr]) * linv[rr];
#pragma unroll
            for (int an = 0; an < 8; an++) {
                int c0 = an * 8 + 2 * tig;
                oacc[an][rr * 2 + 0] += p * relv_s[j * HD + c0];
                oacc[an][rr * 2 + 1] += p * relv_s[j * HD + c0 + 1];
            }
        }
#pragma unroll
        for (int an = 0; an < 8; an++) {
            int c0 = an * 8 + 2 * tig;
            unsigned ub, us;
            cvt2(oacc[an][rr * 2 + 0], oacc[an][rr * 2 + 1], ub, us);
            size_t o = ((size_t)(b * T + qg)) * C + h * HD + c0;
            *reinterpret_cast<unsigned*>(&g_ab[o]) = ub;
            *reinterpret_cast<unsigned*>(&g_as[o]) = us;
        }
    }
}

// ---------------- LN warp-per-row ----------------
__global__ void ln_res_kernel(float* __restrict__ x, const float* __restrict__ r,
                              const float* __restrict__ gg, const float* __restrict__ beta,
                              const int* __restrict__ lens, int apply_mask) {
    int row = blockIdx.x * 8 + (threadIdx.x >> 5);
    int lane = threadIdx.x & 31;
    const float4* xr = (const float4*)(x + (size_t)row * C);
    const float4* rr = (const float4*)(r + (size_t)row * C);
    float4 a0 = xr[lane], a1 = xr[lane + 32];
    float4 b0 = rr[lane], b1 = rr[lane + 32];
    float v[8] = {a0.x + b0.x, a0.y + b0.y, a0.z + b0.z, a0.w + b0.w,
                  a1.x + b1.x, a1.y + b1.y, a1.z + b1.z, a1.w + b1.w};
    float s = 0.f;
#pragma unroll
    for (int i = 0; i < 8; i++) s += v[i];
    float mean = warpReduceSum(s) * (1.0f / C);
    float sq = 0.f;
#pragma unroll
    for (int i = 0; i < 8; i++) {
        float d = v[i] - mean;
        sq += d * d;
    }
    float inv = rsqrtf(warpReduceSum(sq) * (1.0f / C) + 1e-5f);
    float zero = 1.0f;
    if (apply_mask) {
        int b = row >> 10, t = row & (T - 1);
        if (t >= lens[b]) zero = 0.0f;
    }
    const float4* gp = (const float4*)gg;
    const float4* bp = (const float4*)beta;
    float4 g0 = gp[lane], g1 = gp[lane + 32];
    float4 e0 = bp[lane], e1 = bp[lane + 32];
    float gv[8] = {g0.x, g0.y, g0.z, g0.w, g1.x, g1.y, g1.z, g1.w};
    float ev[8] = {e0.x, e0.y, e0.z, e0.w, e1.x, e1.y, e1.z, e1.w};
    float y[8];
#pragma unroll
    for (int i = 0; i < 8; i++) y[i] = ((v[i] - mean) * inv * gv[i] + ev[i]) * zero;

    float4* xo = (float4*)(x + (size_t)row * C);
    xo[lane] = make_float4(y[0], y[1], y[2], y[3]);
    xo[lane + 32] = make_float4(y[4], y[5], y[6], y[7]);
    unsigned* pb16 = (unsigned*)(g_xb + (size_t)row * C);
    unsigned* ps16 = (unsigned*)(g_xs + (size_t)row * C);
#pragma unroll
    for (int i = 0; i < 4; i += 2) {
        unsigned ub, us;
        cvt2(y[i], y[i + 1], ub, us);
        pb16[lane * 2 + i / 2] = ub;
        ps16[lane * 2 + i / 2] = us;
    }
#pragma unroll
    for (int i = 4; i < 8; i += 2) {
        unsigned ub, us;
        cvt2(y[i], y[i + 1], ub, us);
        pb16[64 + lane * 2 + (i - 4) / 2] = ub;
        ps16[64 + lane * 2 + (i - 4) / 2] = us;
    }
}

// ---------------- x (B,T,C) -> out (B,C,T) ----------------
__global__ void transpose_kernel(const float* __restrict__ x, float* __restrict__ out) {
    __shared__ float tile[32][33];
    int b = blockIdx.z;
    int t0 = blockIdx.x * 32, c0 = blockIdx.y * 32;
    int tx = threadIdx.x, ty = threadIdx.y;
#pragma unroll
    for (int i = 0; i < 32; i += 8)
        tile[ty + i][tx] = x[(size_t)(b * T + t0 + ty + i) * C + c0 + tx];
    __syncthreads();
#pragma unroll
    for (int i = 0; i < 32; i += 8)
        out[(size_t)(b * C + c0 + ty + i) * T + t0 + tx] = tile[tx][ty + i];
}

__global__ void mask_out_kernel(const int* __restrict__ lens, float* __restrict__ out_mask) {
    int b = blockIdx.x;
    int len = lens[b];
    for (int t = threadIdx.x; t < T; t += blockDim.x)
        out_mask[(size_t)b * T + t] = (t < len) ? 1.0f : 0.0f;
}

}  // namespace

extern "C" void kernel_launch(void* const* d_in, const int* in_sizes, int n_in,
                              void* d_out, int out_size) {
    (void)in_sizes; (void)n_in; (void)out_size;
    const float* emb   = (const float*)d_in[0];
    const float* Wq    = (const float*)d_in[1];
    const float* Wk    = (const float*)d_in[2];
    const float* Wv    = (const float*)d_in[3];
    const float* Wo    = (const float*)d_in[4];
    const float* bq    = (const float*)d_in[5];
    const float* bk    = (const float*)d_in[6];
    const float* bv    = (const float*)d_in[7];
    const float* bo    = (const float*)d_in[8];
    const float* rel_k = (const float*)d_in[9];
    const float* rel_v = (const float*)d_in[10];
    const float* ln1_g = (const float*)d_in[11];
    const float* ln1_b = (const float*)d_in[12];
    const float* ln2_g = (const float*)d_in[13];
    const float* ln2_b = (const float*)d_in[14];
    const float* fw1   = (const float*)d_in[15];
    const float* fb1   = (const float*)d_in[16];
    const float* fw2   = (const float*)d_in[17];
    const float* fb2   = (const float*)d_in[18];
    const float* pw    = (const float*)d_in[19];
    const float* pb    = (const float*)d_in[20];
    const int*   toks  = (const int*)d_in[21];
    const int*   lens  = (const int*)d_in[22];

    cudaFuncSetAttribute(mma_gemm_p<0>, cudaFuncAttributeMaxDynamicSharedMemorySize, SMEM_BYTES);
    cudaFuncSetAttribute(mma_gemm_p<1>, cudaFuncAttributeMaxDynamicSharedMemorySize, SMEM_BYTES);
    cudaFuncSetAttribute(mma_gemm_p<3>, cudaFuncAttributeMaxDynamicSharedMemorySize, SMEM_BYTES);
    cudaFuncSetAttribute(mma_gemm64, cudaFuncAttributeMaxDynamicSharedMemorySize, G64_SMEM);
    cudaFuncSetAttribute(flash_attn, cudaFuncAttributeMaxDynamicSharedMemorySize, FLASH_SMEM);

    float *px, *ptmp;
    bf16 *pwb, *pws, *pxb, *pxs, *pab, *pas, *pfb, *pfs;
    cudaGetSymbolAddress((void**)&px,   g_x);
    cudaGetSymbolAddress((void**)&ptmp, g_tmp);
    cudaGetSymbolAddress((void**)&pwb,  g_wb);
    cudaGetSymbolAddress((void**)&pws,  g_ws);
    cudaGetSymbolAddress((void**)&pxb,  g_xb);
    cudaGetSymbolAddress((void**)&pxs,  g_xs);
    cudaGetSymbolAddress((void**)&pab,  g_ab);
    cudaGetSymbolAddress((void**)&pas,  g_as);
    cudaGetSymbolAddress((void**)&pfb,  g_fb);
    cudaGetSymbolAddress((void**)&pfs,  g_fs);

    float* out      = (float*)d_out;
    float* out_x    = out;
    float* out_m    = out + (size_t)B * C * T;
    float* out_logs = out_m + (size_t)B * OUT * T;
    float* out_mask = out_logs + (size_t)B * OUT * T;

    prep_kernel<<<6016, 256>>>(Wq, Wk, Wv, Wo, fw1, fw2, pw, emb, toks);

    dim3 gQKV(3 * C / 128, BT / 128);
    dim3 gFC(FC / 128, BT / 128);
    dim3 g64(C / 128, BT / 64);   // (2, 128) = 256 blocks

    for (int l = 0; l < L; l++) {
        size_t qkv = OFF_QKV + (size_t)l * 3 * C * C;
        size_t wo = OFF_WO + (size_t)l * C * C;
        size_t f1 = OFF_F1 + (size_t)l * C * FC;
        size_t f2 = OFF_F2 + (size_t)l * FC * C;

        mma_gemm_p<1><<<gQKV, 256, SMEM_BYTES>>>(
            pxb, pxs, pwb + qkv, pws + qkv, bq + (size_t)l * C, bk + (size_t)l * C,
            bv + (size_t)l * C, nullptr, nullptr, nullptr, nullptr, BT, 3 * C, C, 1.0f, 0,
            nullptr);

        flash_attn<<<dim3(T / 128, B * H), 256, FLASH_SMEM>>>(
            lens, rel_k + (size_t)l * NREL * HD, rel_v + (size_t)l * NREL * HD);

        mma_gemm64<<<g64, 256, G64_SMEM>>>(pab, pas, pwb + wo, pws + wo, bo + (size_t)l * C,
                                           ptmp, C, C);
        ln_res_kernel<<<BT / 8, 256>>>(px, ptmp, ln1_g + (size_t)l * C, ln1_b + (size_t)l * C,
                                       lens, 0);

        mma_gemm_p<0><<<gFC, 256, SMEM_BYTES>>>(pxb, pxs, pwb + f1, pws + f1,
                                                fb1 + (size_t)l * FC, nullptr, nullptr, nullptr,
                                                pfb, pfs, nullptr, BT, FC, C, 1.0f, 1, nullptr);
        mma_gemm64<<<g64, 256, G64_SMEM>>>(pfb, pfs, pwb + f2, pws + f2, fb2 + (size_t)l * C,
                                           ptmp, C, FC);
        ln_res_kernel<<<BT / 8, 256>>>(px, ptmp, ln2_g + (size_t)l * C, ln2_b + (size_t)l * C,
                                       lens, 1);
    }

    transpose_kernel<<<dim3(T / 32, C / 32, B), dim3(32, 8)>>>(px, out_x);
    mma_gemm_p<3><<<dim3(2 * OUT / 128, BT / 128), 256, SMEM_BYTES>>>(
        pxb, pxs, pwb + OFF_PJ, pws + OFF_PJ, pb, nullptr, nullptr, out_m, nullptr, nullptr,
        out_logs, BT, 2 * OUT, C, 1.0f, 0, lens);
    mask_out_kernel<<<B, 256>>>(lens, out_mask);
}